// round 16
// baseline (speedup 1.0000x reference)
#include <cuda_runtime.h>
#include <math.h>
#include <stdint.h>

#define BB   4
#define SS   1024
#define DDIM 1024
#define HH   16
#define DHH  64
#define FF   4096
#define MM   (BB*SS)      // 4096 rows
#define NEGV (-1e20f)

// ---------------- scratch (allocation-free: device globals) ----------------
__device__ float g_q  [MM*DDIM];
__device__ float g_k  [MM*DDIM];
__device__ float g_v  [MM*DDIM];
__device__ float g_ctx[MM*DDIM];
__device__ float g_y1 [MM*DDIM];
__device__ float g_t  [MM*DDIM];
__device__ float g_h  [(size_t)MM*FF];
__device__ float g_y2 [MM*DDIM];

// ---------------- helpers ---------------------------------------------------
__device__ __forceinline__ float to_tf32(float x) {
    float y;
    asm("cvt.rna.tf32.f32 %0, %1;" : "=f"(y) : "f"(x));
    return y;
}
__device__ __forceinline__ uint32_t smem_u32(const void* p) {
    uint32_t a;
    asm("{ .reg .u64 t; cvta.to.shared.u64 t, %1; cvt.u32.u64 %0, t; }"
        : "=r"(a) : "l"(p));
    return a;
}
__device__ __forceinline__ void cpa16(uint32_t dst, const void* src) {
    asm volatile("cp.async.cg.shared.global [%0], [%1], 16;" :: "r"(dst), "l"(src));
}
#define CPA_COMMIT() asm volatile("cp.async.commit_group;" ::: "memory")
#define CPA_WAIT1()  asm volatile("cp.async.wait_group 1;" ::: "memory")
#define CPA_WAIT0()  asm volatile("cp.async.wait_group 0;" ::: "memory")

#define MMA_TF32(d, a, b)                                                      \
    asm volatile("mma.sync.aligned.m16n8k8.row.col.f32.tf32.tf32.f32 "         \
                 "{%0,%1,%2,%3}, {%4,%5,%6,%7}, {%8,%9}, {%0,%1,%2,%3};"       \
                 : "+f"((d)[0]), "+f"((d)[1]), "+f"((d)[2]), "+f"((d)[3])      \
                 : "r"((a)[0]), "r"((a)[1]), "r"((a)[2]), "r"((a)[3]),         \
                   "r"((b)[0]), "r"((b)[1]))

#define SST 20                    // smem row stride in floats
#define STG_BYTES (128*SST*4)     // 10240 B per stage per operand
#define G_SMEM (6*STG_BYTES)      // 3 stages x (A+B) = 61440 B

// Shared GEMM body: C[M,N] = A[M,K] @ W[N,K]^T + bias (+epi).
// 3-stage cp.async pipeline, ONE __syncthreads per chunk (prefetch issued
// post-barrier into the stage freed by the previous iteration's MMAs).
// EPI: 0 = bias, 1 = bias + residual R, 2 = bias + relu
template<int EPI>
__device__ __forceinline__ void mgemm_body(
    const float* __restrict__ A, const float* __restrict__ W,
    const float* __restrict__ bias, const float* __restrict__ R,
    float* __restrict__ C, int M, int N, int K,
    char* sm, int bm, int bn)
{
    const int tid  = threadIdx.x;
    const int lane = tid & 31;
    const int wid  = tid >> 5;
    const int wm   = wid >> 1;        // 0..3 -> warp M offset *32
    const int wn   = wid & 1;         // 0..1 -> warp N offset *64
    const int g    = lane >> 2;       // 0..7
    const int tc   = lane & 3;        // 0..3

    // staging coords: 512 float4 per tile (128 rows x 16 cols)
    const int f0 = tid,        r0s = f0 >> 2, c0s = (f0 & 3) << 2;
    const int f1 = tid + 256,  r1s = f1 >> 2, c1s = (f1 & 3) << 2;

    const float* Ag0 = A + (size_t)(bm + r0s) * K + c0s;
    const float* Ag1 = A + (size_t)(bm + r1s) * K + c1s;
    const float* Wg0 = W + (size_t)(bn + r0s) * K + c0s;
    const float* Wg1 = W + (size_t)(bn + r1s) * K + c1s;

    const uint32_t aBase = smem_u32(sm);
    const uint32_t bBase = aBase + 3u * STG_BYTES;
    const uint32_t offA0 = (uint32_t)(r0s * SST + c0s) * 4u;
    const uint32_t offA1 = (uint32_t)(r1s * SST + c1s) * 4u;

    float acc[2][8][4];
#pragma unroll
    for (int i = 0; i < 2; i++)
#pragma unroll
        for (int j = 0; j < 8; j++)
#pragma unroll
            for (int e = 0; e < 4; e++) acc[i][j][e] = 0.f;

    // prologue: stages 0 and 1 in flight (2 commit groups)
    {
        cpa16(aBase + offA0, Ag0);
        cpa16(aBase + offA1, Ag1);
        cpa16(bBase + offA0, Wg0);
        cpa16(bBase + offA1, Wg1);
        CPA_COMMIT();
        cpa16(aBase + STG_BYTES + offA0, Ag0 + 16);
        cpa16(aBase + STG_BYTES + offA1, Ag1 + 16);
        cpa16(bBase + STG_BYTES + offA0, Wg0 + 16);
        cpa16(bBase + STG_BYTES + offA1, Wg1 + 16);
        CPA_COMMIT();
    }

    const int nch = K >> 4;
    int stage = 0;                               // = ch % 3
    for (int ch = 0; ch < nch; ch++) {
        if (ch + 1 < nch) CPA_WAIT1(); else CPA_WAIT0();
        __syncthreads();                         // stage data visible; prev MMAs done

        if (ch + 2 < nch) {                      // prefetch into freed stage
            int ps = stage + 2; if (ps >= 3) ps -= 3;
            const int k0 = (ch + 2) << 4;
            const uint32_t ao = aBase + (uint32_t)ps * STG_BYTES;
            const uint32_t bo = bBase + (uint32_t)ps * STG_BYTES;
            cpa16(ao + offA0, Ag0 + k0);
            cpa16(ao + offA1, Ag1 + k0);
            cpa16(bo + offA0, Wg0 + k0);
            cpa16(bo + offA1, Wg1 + k0);
            CPA_COMMIT();
        }

        const float* Asb = (const float*)(sm + (size_t)stage * STG_BYTES);
        const float* Bsb = (const float*)(sm + 3u * STG_BYTES + (size_t)stage * STG_BYTES);
#pragma unroll
        for (int kk = 0; kk < 2; kk++) {
            const int k8 = kk * 8;
            uint32_t af[2][4], bf[8][2];
#pragma unroll
            for (int fi = 0; fi < 2; fi++) {
                const float* ap = &Asb[(wm*32 + fi*16 + g) * SST + k8 + tc];
                af[fi][0] = __float_as_uint(ap[0]);
                af[fi][1] = __float_as_uint(ap[8*SST]);
                af[fi][2] = __float_as_uint(ap[4]);
                af[fi][3] = __float_as_uint(ap[8*SST + 4]);
            }
#pragma unroll
            for (int fj = 0; fj < 8; fj++) {
                const float* bp = &Bsb[(wn*64 + fj*8 + g) * SST + k8 + tc];
                bf[fj][0] = __float_as_uint(bp[0]);
                bf[fj][1] = __float_as_uint(bp[4]);
            }
#pragma unroll
            for (int fi = 0; fi < 2; fi++)
#pragma unroll
                for (int fj = 0; fj < 8; fj++)
                    MMA_TF32(acc[fi][fj], af[fi], bf[fj]);
        }
        if (++stage == 3) stage = 0;
    }

    // epilogue: d0,d1 -> (row=g, col=2tc,2tc+1); d2,d3 -> (row=g+8, same)
#pragma unroll
    for (int fi = 0; fi < 2; fi++) {
        const int ra = bm + wm*32 + fi*16 + g;
#pragma unroll
        for (int fj = 0; fj < 8; fj++) {
            const int c = bn + wn*64 + fj*8 + 2*tc;
            const float2 b2 = *(const float2*)(bias + c);
            float x0 = acc[fi][fj][0] + b2.x;
            float x1 = acc[fi][fj][1] + b2.y;
            float x2 = acc[fi][fj][2] + b2.x;
            float x3 = acc[fi][fj][3] + b2.y;
            if (EPI == 2) {
                x0 = fmaxf(x0, 0.f); x1 = fmaxf(x1, 0.f);
                x2 = fmaxf(x2, 0.f); x3 = fmaxf(x3, 0.f);
            }
            if (EPI == 1) {
                const float2 r2a = *(const float2*)(R + (size_t)ra * N + c);
                const float2 r2b = *(const float2*)(R + (size_t)(ra+8) * N + c);
                x0 += r2a.x; x1 += r2a.y; x2 += r2b.x; x3 += r2b.y;
            }
            float2 o0 = make_float2(x0, x1);
            float2 o1 = make_float2(x2, x3);
            *(float2*)(C + (size_t)ra * N + c)     = o0;
            *(float2*)(C + (size_t)(ra+8) * N + c) = o1;
        }
    }
}

template<int EPI>
__global__ __launch_bounds__(256, 2)
void mgemm(const float* __restrict__ A, const float* __restrict__ W,
           const float* __restrict__ bias, const float* __restrict__ R,
           float* __restrict__ C, int M, int N, int K)
{
    extern __shared__ char gsm[];
    mgemm_body<EPI>(A, W, bias, R, C, M, N, K, gsm,
                    blockIdx.y * 128, blockIdx.x * 128);
}

// fused QKV: blockIdx.z selects (W, bias, C); one launch = 3x the CTAs.
__global__ __launch_bounds__(256, 2)
void qkv_gemm(const float* __restrict__ A,
              const float* __restrict__ wq, const float* __restrict__ bq,
              const float* __restrict__ wk, const float* __restrict__ bk,
              const float* __restrict__ wv, const float* __restrict__ bv,
              float* __restrict__ q, float* __restrict__ k, float* __restrict__ v)
{
    extern __shared__ char gsm[];
    const int z = blockIdx.z;
    const float* W    = (z == 0) ? wq : (z == 1) ? wk : wv;
    const float* bias = (z == 0) ? bq : (z == 1) ? bk : bv;
    float*       C    = (z == 0) ? q  : (z == 1) ? k  : v;
    mgemm_body<0>(A, W, bias, nullptr, C, MM, DDIM, DDIM, gsm,
                  blockIdx.y * 128, blockIdx.x * 128);
}

// ---------------- tf32 mma flash attention ----------------------------------
// CTA: 128 threads (4 warps). Q-tile 64 (16 rows/warp), K-tile 64, DH=64.
// smem stride 68 (== 4 mod 32) -> conflict-free fragment LDS.
#define AST 68
#define ATTN_SMEM_B (3*64*AST*4 + 64*4)

__global__ __launch_bounds__(128)
void attn_mma(const int* __restrict__ mask)
{
    extern __shared__ float smf[];
    float* Ks  = smf;              // 64 x AST  (key x dh), tf32
    float* Vts = Ks  + 64*AST;     // 64 x AST  (dh x key), tf32
    float* Ps  = Vts + 64*AST;     // 64 x AST  (q x key), tf32; also Q staging
    int*   mS  = (int*)(Ps + 64*AST);

    const int q0   = blockIdx.x * 64;
    const int h    = blockIdx.y;
    const int b    = blockIdx.z;
    const int tid  = threadIdx.x;
    const int wid  = tid >> 5, lane = tid & 31;
    const int g    = lane >> 2, tc = lane & 3;
    const int w16  = wid * 16;

    const float* Qg = g_q + (size_t)(b*SS)*DDIM + h*DHH;
    const float* Kg = g_k + (size_t)(b*SS)*DDIM + h*DHH;
    const float* Vg = g_v + (size_t)(b*SS)*DDIM + h*DHH;

    // stage Q (scaled by 1/8, tf32) into Ps region, then load fragments to regs
#pragma unroll
    for (int it = 0; it < 8; it++) {
        int f = tid + 128*it;                 // 1024 float4 = 64 x 64
        int r = f >> 4, c4 = (f & 15) << 2;
        float4 v = *(const float4*)(Qg + (size_t)(q0 + r)*DDIM + c4);
        Ps[r*AST + c4 + 0] = to_tf32(v.x * 0.125f);
        Ps[r*AST + c4 + 1] = to_tf32(v.y * 0.125f);
        Ps[r*AST + c4 + 2] = to_tf32(v.z * 0.125f);
        Ps[r*AST + c4 + 3] = to_tf32(v.w * 0.125f);
    }
    __syncthreads();

    uint32_t aq[8][4];
#pragma unroll
    for (int ks = 0; ks < 8; ks++) {
        const float* ap = &Ps[(w16 + g)*AST + ks*8 + tc];
        aq[ks][0] = __float_as_uint(ap[0]);
        aq[ks][1] = __float_as_uint(ap[8*AST]);
        aq[ks][2] = __float_as_uint(ap[4]);
        aq[ks][3] = __float_as_uint(ap[8*AST + 4]);
    }

    float m0 = -3e38f, m1 = -3e38f, l0 = 0.f, l1 = 0.f;
    float acc[8][4];
#pragma unroll
    for (int fj = 0; fj < 8; fj++)
#pragma unroll
        for (int e = 0; e < 4; e++) acc[fj][e] = 0.f;

    for (int kt = 0; kt < SS/64; kt++) {
        __syncthreads();                      // protect Ks/Vts (and Ps on kt=0)
        const int kbase = kt * 64;
        // stage K (tf32) and V transposed (tf32)
#pragma unroll
        for (int it = 0; it < 8; it++) {
            int f = tid + 128*it;
            int r = f >> 4, c4 = (f & 15) << 2;
            float4 kv = *(const float4*)(Kg + (size_t)(kbase + r)*DDIM + c4);
            Ks[r*AST + c4 + 0] = to_tf32(kv.x);
            Ks[r*AST + c4 + 1] = to_tf32(kv.y);
            Ks[r*AST + c4 + 2] = to_tf32(kv.z);
            Ks[r*AST + c4 + 3] = to_tf32(kv.w);
            float4 vv = *(const float4*)(Vg + (size_t)(kbase + r)*DDIM + c4);
            Vts[(c4+0)*AST + r] = to_tf32(vv.x);
            Vts[(c4+1)*AST + r] = to_tf32(vv.y);
            Vts[(c4+2)*AST + r] = to_tf32(vv.z);
            Vts[(c4+3)*AST + r] = to_tf32(vv.w);
        }
        if (tid < 64) mS[tid] = mask[b*SS + kbase + tid];
        __syncthreads();

        // S = Q K^T  (warp: 16 q-rows x 64 keys)
        float sa[8][4];
#pragma unroll
        for (int fj = 0; fj < 8; fj++)
#pragma unroll
            for (int e = 0; e < 4; e++) sa[fj][e] = 0.f;
#pragma unroll
        for (int ks = 0; ks < 8; ks++) {
            uint32_t bf[8][2];
#pragma unroll
            for (int fj = 0; fj < 8; fj++) {
                const float* bp = &Ks[(fj*8 + g)*AST + ks*8 + tc];
                bf[fj][0] = __float_as_uint(bp[0]);
                bf[fj][1] = __float_as_uint(bp[4]);
            }
#pragma unroll
            for (int fj = 0; fj < 8; fj++)
                MMA_TF32(sa[fj], aq[ks], bf[fj]);
        }

        // mask
#pragma unroll
        for (int fj = 0; fj < 8; fj++) {
            const int c = fj*8 + 2*tc;
            if (mS[c]   == 0) { sa[fj][0] = NEGV; sa[fj][2] = NEGV; }
            if (mS[c+1] == 0) { sa[fj][1] = NEGV; sa[fj][3] = NEGV; }
        }

        // online softmax (rows g and g+8); quad reduction over tc lanes
        float mt0 = -3e38f, mt1 = -3e38f;
#pragma unroll
        for (int fj = 0; fj < 8; fj++) {
            mt0 = fmaxf(mt0, fmaxf(sa[fj][0], sa[fj][1]));
            mt1 = fmaxf(mt1, fmaxf(sa[fj][2], sa[fj][3]));
        }
        mt0 = fmaxf(mt0, __shfl_xor_sync(0xffffffffu, mt0, 1));
        mt0 = fmaxf(mt0, __shfl_xor_sync(0xffffffffu, mt0, 2));
        mt1 = fmaxf(mt1, __shfl_xor_sync(0xffffffffu, mt1, 1));
        mt1 = fmaxf(mt1, __shfl_xor_sync(0xffffffffu, mt1, 2));
        const float mn0 = fmaxf(m0, mt0), mn1 = fmaxf(m1, mt1);
        const float f0 = __expf(m0 - mn0), f1 = __expf(m1 - mn1);
        m0 = mn0; m1 = mn1;

        float rs0 = 0.f, rs1 = 0.f;
#pragma unroll
        for (int fj = 0; fj < 8; fj++) {
            float p0 = __expf(sa[fj][0] - mn0);
            float p1 = __expf(sa[fj][1] - mn0);
            float p2 = __expf(sa[fj][2] - mn1);
            float p3 = __expf(sa[fj][3] - mn1);
            rs0 += p0 + p1; rs1 += p2 + p3;
            *(float2*)&Ps[(w16 + g  )*AST + fj*8 + 2*tc] = make_float2(to_tf32(p0), to_tf32(p1));
            *(float2*)&Ps[(w16 + g+8)*AST + fj*8 + 2*tc] = make_float2(to_tf32(p2), to_tf32(p3));
        }
        rs0 += __shfl_xor_sync(0xffffffffu, rs0, 1);
        rs0 += __shfl_xor_sync(0xffffffffu, rs0, 2);
        rs1 += __shfl_xor_sync(0xffffffffu, rs1, 1);
        rs1 += __shfl_xor_sync(0xffffffffu, rs1, 2);
        l0 = l0 * f0 + rs0;
        l1 = l1 * f1 + rs1;
#pragma unroll
        for (int fj = 0; fj < 8; fj++) {
            acc[fj][0] *= f0; acc[fj][1] *= f0;
            acc[fj][2] *= f1; acc[fj][3] *= f1;
        }
        __syncwarp();

        // O += P Vt  (A = own Ps rows, B = Vts)
#pragma unroll
        for (int ks = 0; ks < 8; ks++) {
            uint32_t ap2[4];
            const float* pp = &Ps[(w16 + g)*AST + ks*8 + tc];
            ap2[0] = __float_as_uint(pp[0]);
            ap2[1] = __float_as_uint(pp[8*AST]);
            ap2[2] = __float_as_uint(pp[4]);
            ap2[3] = __float_as_uint(pp[8*AST + 4]);
#pragma unroll
            for (int fj = 0; fj < 8; fj++) {
                const float* bp = &Vts[(fj*8 + g)*AST + ks*8 + tc];
                uint32_t bf2[2] = { __float_as_uint(bp[0]), __float_as_uint(bp[4]) };
                MMA_TF32(acc[fj], ap2, bf2);
            }
        }
    }

    // write O / l
    const float inv0 = 1.f / l0, inv1 = 1.f / l1;
    float* Og = g_ctx + (size_t)(b*SS)*DDIM + h*DHH;
#pragma unroll
    for (int fj = 0; fj < 8; fj++) {
        const int c = fj*8 + 2*tc;
        *(float2*)(Og + (size_t)(q0 + w16 + g  )*DDIM + c) =
            make_float2(acc[fj][0]*inv0, acc[fj][1]*inv0);
        *(float2*)(Og + (size_t)(q0 + w16 + g+8)*DDIM + c) =
            make_float2(acc[fj][2]*inv1, acc[fj][3]*inv1);
    }
}

// ---------------- LayerNorm over D=1024, one CTA per row --------------------
__global__ __launch_bounds__(256)
void ln_kernel(const float* __restrict__ y, const float* __restrict__ g,
               const float* __restrict__ bta, const int* __restrict__ mask,
               float* __restrict__ out)
{
    const int row = blockIdx.x;
    const int tid = threadIdx.x;
    const float* yr = y + (size_t)row * DDIM;
    __shared__ float red[8];

    float4 xv = *(const float4*)(yr + tid*4);
    float s = xv.x + xv.y + xv.z + xv.w;
#pragma unroll
    for (int o = 16; o > 0; o >>= 1) s += __shfl_xor_sync(0xffffffffu, s, o);
    if ((tid & 31) == 0) red[tid >> 5] = s;
    __syncthreads();
    s = 0.f;
#pragma unroll
    for (int w = 0; w < 8; w++) s += red[w];
    const float mean = s * (1.f / DDIM);

    float dx0 = xv.x - mean, dx1 = xv.y - mean, dx2 = xv.z - mean, dx3 = xv.w - mean;
    float s2 = dx0*dx0 + dx1*dx1 + dx2*dx2 + dx3*dx3;
    __syncthreads();
#pragma unroll
    for (int o = 16; o > 0; o >>= 1) s2 += __shfl_xor_sync(0xffffffffu, s2, o);
    if ((tid & 31) == 0) red[tid >> 5] = s2;
    __syncthreads();
    s2 = 0.f;
#pragma unroll
    for (int w = 0; w < 8; w++) s2 += red[w];
    const float rstd = rsqrtf(s2 * (1.f / DDIM) + 1e-5f);

    const float mv = mask ? (float)mask[row] : 1.f;
    float4 gv = *(const float4*)(g   + tid*4);
    float4 bv = *(const float4*)(bta + tid*4);
    float4 ov;
    ov.x = (dx0 * rstd * gv.x + bv.x) * mv;
    ov.y = (dx1 * rstd * gv.y + bv.y) * mv;
    ov.z = (dx2 * rstd * gv.z + bv.z) * mv;
    ov.w = (dx3 * rstd * gv.w + bv.w) * mv;
    *(float4*)(out + (size_t)row * DDIM + tid*4) = ov;
}

// ---------------- launch --------------------------------------------------
extern "C" void kernel_launch(void* const* d_in, const int* in_sizes, int n_in,
                              void* d_out, int out_size)
{
    const float* x    = (const float*)d_in[0];
    const int*   mask = (const int*)  d_in[1];
    const float* wq = (const float*)d_in[2];  const float* bq = (const float*)d_in[3];
    const float* wk = (const float*)d_in[4];  const float* bk = (const float*)d_in[5];
    const float* wv = (const float*)d_in[6];  const float* bv = (const float*)d_in[7];
    const float* wo = (const float*)d_in[8];  const float* bo = (const float*)d_in[9];
    const float* l1g = (const float*)d_in[10]; const float* l1b = (const float*)d_in[11];
    const float* w1 = (const float*)d_in[12]; const float* b1 = (const float*)d_in[13];
    const float* w2 = (const float*)d_in[14]; const float* b2 = (const float*)d_in[15];
    const float* l2g = (const float*)d_in[16]; const float* l2b = (const float*)d_in[17];

    float *q, *k, *v, *ctx, *y1, *t, *hb, *y2;
    cudaGetSymbolAddress((void**)&q,   g_q);
    cudaGetSymbolAddress((void**)&k,   g_k);
    cudaGetSymbolAddress((void**)&v,   g_v);
    cudaGetSymbolAddress((void**)&ctx, g_ctx);
    cudaGetSymbolAddress((void**)&y1,  g_y1);
    cudaGetSymbolAddress((void**)&t,   g_t);
    cudaGetSymbolAddress((void**)&hb,  g_h);
    cudaGetSymbolAddress((void**)&y2,  g_y2);

    cudaFuncSetAttribute(attn_mma, cudaFuncAttributeMaxDynamicSharedMemorySize, ATTN_SMEM_B);
    cudaFuncSetAttribute(mgemm<1>, cudaFuncAttributeMaxDynamicSharedMemorySize, G_SMEM);
    cudaFuncSetAttribute(mgemm<2>, cudaFuncAttributeMaxDynamicSharedMemorySize, G_SMEM);
    cudaFuncSetAttribute(qkv_gemm, cudaFuncAttributeMaxDynamicSharedMemorySize, G_SMEM);

    dim3 gD(DDIM/128, MM/128);      // 8 x 32
    dim3 gF(FF/128,   MM/128);      // 32 x 32
    dim3 gQKV(DDIM/128, MM/128, 3); // 8 x 32 x 3

    qkv_gemm<<<gQKV, 256, G_SMEM>>>(x, wq, bq, wk, bk, wv, bv, q, k, v);

    attn_mma<<<dim3(SS/64, HH, BB), 128, ATTN_SMEM_B>>>(mask);

    mgemm<1><<<gD, 256, G_SMEM>>>(ctx, wo, bo, x,       y1, MM, DDIM, DDIM);
    ln_kernel<<<MM, 256>>>(y1, l1g, l1b, nullptr, t);

    mgemm<2><<<gF, 256, G_SMEM>>>(t,   w1, b1, nullptr, hb, MM, FF,   DDIM);
    mgemm<1><<<gD, 256, G_SMEM>>>(hb,  w2, b2, t,       y2, MM, DDIM, FF);
    ln_kernel<<<MM, 256>>>(y2, l2g, l2b, mask, (float*)d_out);
}